// round 4
// baseline (speedup 1.0000x reference)
#include <cuda_runtime.h>
#include <cuda_bf16.h>
#include <cstdint>

// ---------------- problem constants ----------------
#define B_SZ 16384
#define P_N  128
#define V_N  128
#define W_N  64
#define BN_EPS 1e-5
#define RB_N  (B_SZ / 128)   // 128 row-blocks

// ---------------- scratch (static device globals; no allocation) ----------------
__device__ float          g_p[P_N * B_SZ];          // p[pathway][batch], 8 MB
__device__ __nv_bfloat16  g_W1bf[P_N * W_N * V_N];  // bf16 W1, row-major [p][w][v], 2 MB
__device__ float2         g_part[RB_N * P_N];       // per-(rb, p) partial (sum, sumsq), 128 KB
__device__ float          g_a[P_N];
__device__ float          g_c;

__device__ __forceinline__ uint32_t smem_u32(const void* p) {
    uint32_t a;
    asm("{ .reg .u64 t; cvta.to.shared.u64 t, %1; cvt.u32.u64 %0, t; }" : "=r"(a) : "l"(p));
    return a;
}

// swizzled byte offset inside a [rows][128 bf16] tile (256 B per row)
__device__ __forceinline__ int swz(int row, int byte_in_row) {
    return row * 256 + (byte_in_row ^ ((row & 7) << 4));
}

__device__ __forceinline__ void ldmatrix_x4(uint32_t& r0, uint32_t& r1, uint32_t& r2, uint32_t& r3,
                                            uint32_t addr) {
    asm volatile("ldmatrix.sync.aligned.m8n8.x4.shared.b16 {%0,%1,%2,%3}, [%4];"
                 : "=r"(r0), "=r"(r1), "=r"(r2), "=r"(r3) : "r"(addr));
}

__device__ __forceinline__ void mma_bf16(float& c0, float& c1, float& c2, float& c3,
                                         uint32_t a0, uint32_t a1, uint32_t a2, uint32_t a3,
                                         uint32_t b0, uint32_t b1) {
    asm volatile("mma.sync.aligned.m16n8k16.row.col.f32.bf16.bf16.f32 "
                 "{%0,%1,%2,%3}, {%4,%5,%6,%7}, {%8,%9}, {%0,%1,%2,%3};"
                 : "+f"(c0), "+f"(c1), "+f"(c2), "+f"(c3)
                 : "r"(a0), "r"(a1), "r"(a2), "r"(a3), "r"(b0), "r"(b1));
}

// ============ K0: convert W1 fp32 -> bf16 row-major ============
__global__ __launch_bounds__(256) void k0_w1bf(const float* __restrict__ W1) {
    int idx = blockIdx.x * 256 + threadIdx.x;      // < 262144, each handles 4 elems
    float4 v = *reinterpret_cast<const float4*>(W1 + (size_t)idx * 4);
    __nv_bfloat162 lo = __float22bfloat162_rn(make_float2(v.x, v.y));
    __nv_bfloat162 hi = __float22bfloat162_rn(make_float2(v.z, v.w));
    uint2 pack = make_uint2(*reinterpret_cast<uint32_t*>(&lo), *reinterpret_cast<uint32_t*>(&hi));
    *reinterpret_cast<uint2*>(g_W1bf + (size_t)idx * 4) = pack;
}

// ============ K1: per-pathway [128x64x128] bf16 mma.sync + fused leaky/W2/leaky
//               + per-CTA BN partial stats ============
// grid (B/128, P), 256 threads (8 warps). Warp w: rows m0 = 16*w.
// smem: [0,32768) x tile (swizzled bf16), [32768,49152) W1 tile (swizzled bf16).
// After the mainloop the first 64 B of the x tile are reused as the warp-reduction buffer.
__global__ __launch_bounds__(256) void k1_mma(const float* __restrict__ x,
                                              const float* __restrict__ W2) {
    extern __shared__ char smem[];
    const uint32_t sb = smem_u32(smem);
    const int tid = threadIdx.x;
    const int wid = tid >> 5;
    const int lid = tid & 31;
    const int rb = blockIdx.x;                     // 128-row batch block
    const int p  = blockIdx.y;                     // pathway

    // ---- load + convert x tile: 128 rows x 128 fp32 -> bf16 swizzled smem ----
    {
        const float* xrow = x + (size_t)rb * 128 * (P_N * V_N) + (size_t)p * V_N;
        #pragma unroll
        for (int i = 0; i < 16; i++) {
            int idx = tid + i * 256;               // < 4096
            int r = idx >> 5;
            int c = (idx & 31);                    // float4 index in row
            float4 v = *reinterpret_cast<const float4*>(xrow + (size_t)r * (P_N * V_N) + c * 4);
            __nv_bfloat162 lo = __float22bfloat162_rn(make_float2(v.x, v.y));
            __nv_bfloat162 hi = __float22bfloat162_rn(make_float2(v.z, v.w));
            uint2 pack = make_uint2(*reinterpret_cast<uint32_t*>(&lo), *reinterpret_cast<uint32_t*>(&hi));
            *reinterpret_cast<uint2*>(smem + swz(r, c * 8)) = pack;
        }
    }
    // ---- copy W1 bf16 tile: 64 rows x 128 -> swizzled smem ----
    {
        const uint4* wsrc = reinterpret_cast<const uint4*>(g_W1bf + (size_t)p * (W_N * V_N));
        #pragma unroll
        for (int i = 0; i < 4; i++) {
            int idx = tid + i * 256;               // < 1024 16B-chunks
            int n = idx >> 4;
            int kc = idx & 15;
            *reinterpret_cast<uint4*>(smem + 32768 + swz(n, kc * 16)) = wsrc[idx];
        }
    }
    __syncthreads();

    // ---- mainloop: warp computes [16 x 64], K=128 ----
    float acc[8][4];
    #pragma unroll
    for (int t = 0; t < 8; t++)
        #pragma unroll
        for (int j = 0; j < 4; j++) acc[t][j] = 0.f;

    const int m0 = wid * 16;
    const uint32_t a_row = m0 + (lid & 15);
    const uint32_t a_chunk = (lid >> 4) * 16;
    const int bg = lid >> 3;                        // 0..3 address group
    const int b_nrow_off = (lid & 7) + ((bg >= 2) ? 8 : 0);
    const int b_koff = (bg & 1) * 16;

    #pragma unroll
    for (int ks = 0; ks < 8; ks++) {
        const int kb = ks * 32;                     // byte offset of k-step in row
        uint32_t a0, a1, a2, a3;
        ldmatrix_x4(a0, a1, a2, a3, sb + swz(a_row, kb + a_chunk));
        #pragma unroll
        for (int t = 0; t < 4; t++) {
            uint32_t b0, b1, b2, b3;
            ldmatrix_x4(b0, b1, b2, b3,
                        sb + 32768 + swz(t * 16 + b_nrow_off, kb + b_koff));
            mma_bf16(acc[2*t][0], acc[2*t][1], acc[2*t][2], acc[2*t][3],
                     a0, a1, a2, a3, b0, b1);
            mma_bf16(acc[2*t+1][0], acc[2*t+1][1], acc[2*t+1][2], acc[2*t+1][3],
                     a0, a1, a2, a3, b2, b3);
        }
    }

    // ---- epilogue: h=leaky(acc); dot with W2 over n; p=leaky(dot); BN partials ----
    {
        const float2* w2p = reinterpret_cast<const float2*>(W2 + (size_t)p * W_N);
        float sum0 = 0.f, sum1 = 0.f;               // rows (lid>>2), (lid>>2)+8
        #pragma unroll
        for (int t = 0; t < 8; t++) {
            float2 w2v = __ldg(&w2p[t * 4 + (lid & 3)]);   // cols t*8 + (lid&3)*2, +1
            float h;
            h = acc[t][0]; h = (h >= 0.f) ? h : 0.2f * h; sum0 += h * w2v.x;
            h = acc[t][1]; h = (h >= 0.f) ? h : 0.2f * h; sum0 += h * w2v.y;
            h = acc[t][2]; h = (h >= 0.f) ? h : 0.2f * h; sum1 += h * w2v.x;
            h = acc[t][3]; h = (h >= 0.f) ? h : 0.2f * h; sum1 += h * w2v.y;
        }
        // reduce across the 4 lanes of each quad (butterfly -> replicated in quad)
        sum0 += __shfl_xor_sync(0xFFFFFFFF, sum0, 1);
        sum0 += __shfl_xor_sync(0xFFFFFFFF, sum0, 2);
        sum1 += __shfl_xor_sync(0xFFFFFFFF, sum1, 1);
        sum1 += __shfl_xor_sync(0xFFFFFFFF, sum1, 2);
        float pv0 = (sum0 >= 0.f) ? sum0 : 0.2f * sum0;
        float pv1 = (sum1 >= 0.f) ? sum1 : 0.2f * sum1;
        if ((lid & 3) == 0) {
            int row = lid >> 2;
            float* dst = g_p + (size_t)p * B_SZ + rb * 128 + m0;
            dst[row] = pv0;
            dst[row + 8] = pv1;
        }
        // BN partial stats for this CTA's 128 rows (count each quad once)
        float s1 = ((lid & 3) == 0) ? (pv0 + pv1) : 0.f;
        float s2 = ((lid & 3) == 0) ? (pv0 * pv0 + pv1 * pv1) : 0.f;
        #pragma unroll
        for (int m = 4; m < 32; m <<= 1) {
            s1 += __shfl_xor_sync(0xFFFFFFFF, s1, m);
            s2 += __shfl_xor_sync(0xFFFFFFFF, s2, m);
        }
        // all warps are past their smem reads now; reuse x-tile smem for the 8-entry reduction
        __syncthreads();
        float2* red = reinterpret_cast<float2*>(smem);
        if (lid == 0) red[wid] = make_float2(s1, s2);
        __syncthreads();
        if (tid == 0) {
            float t1 = 0.f, t2 = 0.f;
            #pragma unroll
            for (int w = 0; w < 8; w++) { t1 += red[w].x; t2 += red[w].y; }
            g_part[rb * P_N + p] = make_float2(t1, t2);
        }
    }
}

// ============ K2: reduce partials + collapse BN + global-L2 + projection into a_p, c ============
__global__ __launch_bounds__(128) void k2_finalize(
    const float* __restrict__ gamma, const float* __restrict__ beta,
    const float* __restrict__ Wd, const float* __restrict__ bdp) {
    const int p = threadIdx.x;
    // reduce per-rb partials for this pathway (coalesced across threads)
    double S1 = 0.0, S2 = 0.0;
    #pragma unroll 8
    for (int rb = 0; rb < RB_N; rb++) {
        float2 v = g_part[rb * P_N + p];
        S1 += (double)v.x;
        S2 += (double)v.y;
    }
    const double Bd = (double)B_SZ;
    double mean = S1 / Bd;
    double var = S2 / Bd - mean * mean;
    if (var < 0.0) var = 0.0;
    double sig2 = var + (double)BN_EPS;
    double inv_sigma = 1.0 / sqrt(sig2);
    double g = (double)gamma[p], bt = (double)beta[p], wd = (double)Wd[p];
    double nsq = g * g * Bd * var / sig2 + Bd * bt * bt;   // sum over b of pn^2 for this p
    double t = (bt - mean * g * inv_sigma) * wd;

    __shared__ double sn[128], st[128];
    sn[p] = nsq; st[p] = t;
    __syncthreads();
    for (int o = 64; o > 0; o >>= 1) {
        if (p < o) { sn[p] += sn[p + o]; st[p] += st[p + o]; }
        __syncthreads();
    }
    __shared__ double norm_s, T_s;
    if (p == 0) { norm_s = sqrt(sn[0]); T_s = st[0]; }
    __syncthreads();
    double norm = norm_s;
    g_a[p] = (float)(g * wd * inv_sigma / norm);
    if (p == 0) g_c = (float)(T_s / norm + (double)bdp[0]);
}

// ============ K3: out[b] = sigmoid(sum_p p[b,p]*a_p + c) ============
__global__ __launch_bounds__(256) void k3_out(float* __restrict__ out) {
    __shared__ float sa[128];
    __shared__ float sc;
    const int tid = threadIdx.x;
    if (tid < 128) sa[tid] = g_a[tid];
    if (tid == 0) sc = g_c;
    __syncthreads();
    const int b = blockIdx.x * 256 + tid;
    float acc = 0.f;
    #pragma unroll 8
    for (int p = 0; p < P_N; p++) acc += g_p[(size_t)p * B_SZ + b] * sa[p];
    float z = acc + sc;
    out[b] = 1.f / (1.f + expf(-z));
}

// ============ launch ============
extern "C" void kernel_launch(void* const* d_in, const int* in_sizes, int n_in,
                              void* d_out, int out_size) {
    const float* x     = (const float*)d_in[0];
    const float* W1    = (const float*)d_in[1];
    const float* W2    = (const float*)d_in[2];
    const float* gamma = (const float*)d_in[3];
    const float* beta  = (const float*)d_in[4];
    const float* Wd    = (const float*)d_in[5];
    const float* bdp   = (const float*)d_in[6];
    float* out = (float*)d_out;

    k0_w1bf<<<1024, 256>>>(W1);
    k1_mma<<<dim3(B_SZ / 128, P_N), 256, 49152>>>(x, W2);
    k2_finalize<<<1, 128>>>(gamma, beta, Wd, bdp);
    k3_out<<<B_SZ / 256, 256>>>(out);
}

// round 5
// speedup vs baseline: 1.0355x; 1.0355x over previous
#include <cuda_runtime.h>
#include <cuda_bf16.h>
#include <cstdint>

// ---------------- problem constants ----------------
#define B_SZ 16384
#define P_N  128
#define V_N  128
#define W_N  64
#define BN_EPS 1e-5
#define RB_N  (B_SZ / 128)   // 128 row-blocks

// ---------------- scratch (static device globals; no allocation) ----------------
__device__ float          g_p[P_N * B_SZ];          // p[pathway][batch], 8 MB
__device__ __nv_bfloat16  g_W1bf[P_N * W_N * V_N];  // bf16 W1, row-major [p][w][v], 2 MB
__device__ float2         g_part[RB_N * P_N];       // per-(rb, p) partial (sum, sumsq), 128 KB
__device__ float          g_a[P_N];
__device__ float          g_c;

__device__ __forceinline__ uint32_t smem_u32(const void* p) {
    uint32_t a;
    asm("{ .reg .u64 t; cvta.to.shared.u64 t, %1; cvt.u32.u64 %0, t; }" : "=r"(a) : "l"(p));
    return a;
}

// swizzled byte offset inside a [rows][128 bf16] tile (256 B per row)
__device__ __forceinline__ int swz(int row, int byte_in_row) {
    return row * 256 + (byte_in_row ^ ((row & 7) << 4));
}

__device__ __forceinline__ void ldmatrix_x4(uint32_t& r0, uint32_t& r1, uint32_t& r2, uint32_t& r3,
                                            uint32_t addr) {
    asm volatile("ldmatrix.sync.aligned.m8n8.x4.shared.b16 {%0,%1,%2,%3}, [%4];"
                 : "=r"(r0), "=r"(r1), "=r"(r2), "=r"(r3) : "r"(addr));
}

__device__ __forceinline__ void mma_bf16(float& c0, float& c1, float& c2, float& c3,
                                         uint32_t a0, uint32_t a1, uint32_t a2, uint32_t a3,
                                         uint32_t b0, uint32_t b1) {
    asm volatile("mma.sync.aligned.m16n8k16.row.col.f32.bf16.bf16.f32 "
                 "{%0,%1,%2,%3}, {%4,%5,%6,%7}, {%8,%9}, {%0,%1,%2,%3};"
                 : "+f"(c0), "+f"(c1), "+f"(c2), "+f"(c3)
                 : "r"(a0), "r"(a1), "r"(a2), "r"(a3), "r"(b0), "r"(b1));
}

// ============ K0: convert W1 fp32 -> bf16 row-major ============
__global__ __launch_bounds__(256) void k0_w1bf(const float* __restrict__ W1) {
    int idx = blockIdx.x * 256 + threadIdx.x;      // < 262144, each handles 4 elems
    float4 v = *reinterpret_cast<const float4*>(W1 + (size_t)idx * 4);
    __nv_bfloat162 lo = __float22bfloat162_rn(make_float2(v.x, v.y));
    __nv_bfloat162 hi = __float22bfloat162_rn(make_float2(v.z, v.w));
    uint2 pack = make_uint2(*reinterpret_cast<uint32_t*>(&lo), *reinterpret_cast<uint32_t*>(&hi));
    *reinterpret_cast<uint2*>(g_W1bf + (size_t)idx * 4) = pack;
}

// ============ K1: per-pathway [128x64x128] bf16 mma.sync + fused leaky/W2/leaky
//               + per-CTA BN partial stats  (UNCHANGED from R4 for clean A/B) ============
__global__ __launch_bounds__(256) void k1_mma(const float* __restrict__ x,
                                              const float* __restrict__ W2) {
    extern __shared__ char smem[];
    const uint32_t sb = smem_u32(smem);
    const int tid = threadIdx.x;
    const int wid = tid >> 5;
    const int lid = tid & 31;
    const int rb = blockIdx.x;                     // 128-row batch block
    const int p  = blockIdx.y;                     // pathway

    // ---- load + convert x tile: 128 rows x 128 fp32 -> bf16 swizzled smem ----
    {
        const float* xrow = x + (size_t)rb * 128 * (P_N * V_N) + (size_t)p * V_N;
        #pragma unroll
        for (int i = 0; i < 16; i++) {
            int idx = tid + i * 256;               // < 4096
            int r = idx >> 5;
            int c = (idx & 31);                    // float4 index in row
            float4 v = *reinterpret_cast<const float4*>(xrow + (size_t)r * (P_N * V_N) + c * 4);
            __nv_bfloat162 lo = __float22bfloat162_rn(make_float2(v.x, v.y));
            __nv_bfloat162 hi = __float22bfloat162_rn(make_float2(v.z, v.w));
            uint2 pack = make_uint2(*reinterpret_cast<uint32_t*>(&lo), *reinterpret_cast<uint32_t*>(&hi));
            *reinterpret_cast<uint2*>(smem + swz(r, c * 8)) = pack;
        }
    }
    // ---- copy W1 bf16 tile: 64 rows x 128 -> swizzled smem ----
    {
        const uint4* wsrc = reinterpret_cast<const uint4*>(g_W1bf + (size_t)p * (W_N * V_N));
        #pragma unroll
        for (int i = 0; i < 4; i++) {
            int idx = tid + i * 256;               // < 1024 16B-chunks
            int n = idx >> 4;
            int kc = idx & 15;
            *reinterpret_cast<uint4*>(smem + 32768 + swz(n, kc * 16)) = wsrc[idx];
        }
    }
    __syncthreads();

    // ---- mainloop: warp computes [16 x 64], K=128 ----
    float acc[8][4];
    #pragma unroll
    for (int t = 0; t < 8; t++)
        #pragma unroll
        for (int j = 0; j < 4; j++) acc[t][j] = 0.f;

    const int m0 = wid * 16;
    const uint32_t a_row = m0 + (lid & 15);
    const uint32_t a_chunk = (lid >> 4) * 16;
    const int bg = lid >> 3;                        // 0..3 address group
    const int b_nrow_off = (lid & 7) + ((bg >= 2) ? 8 : 0);
    const int b_koff = (bg & 1) * 16;

    #pragma unroll
    for (int ks = 0; ks < 8; ks++) {
        const int kb = ks * 32;                     // byte offset of k-step in row
        uint32_t a0, a1, a2, a3;
        ldmatrix_x4(a0, a1, a2, a3, sb + swz(a_row, kb + a_chunk));
        #pragma unroll
        for (int t = 0; t < 4; t++) {
            uint32_t b0, b1, b2, b3;
            ldmatrix_x4(b0, b1, b2, b3,
                        sb + 32768 + swz(t * 16 + b_nrow_off, kb + b_koff));
            mma_bf16(acc[2*t][0], acc[2*t][1], acc[2*t][2], acc[2*t][3],
                     a0, a1, a2, a3, b0, b1);
            mma_bf16(acc[2*t+1][0], acc[2*t+1][1], acc[2*t+1][2], acc[2*t+1][3],
                     a0, a1, a2, a3, b2, b3);
        }
    }

    // ---- epilogue: h=leaky(acc); dot with W2 over n; p=leaky(dot); BN partials ----
    {
        const float2* w2p = reinterpret_cast<const float2*>(W2 + (size_t)p * W_N);
        float sum0 = 0.f, sum1 = 0.f;               // rows (lid>>2), (lid>>2)+8
        #pragma unroll
        for (int t = 0; t < 8; t++) {
            float2 w2v = __ldg(&w2p[t * 4 + (lid & 3)]);   // cols t*8 + (lid&3)*2, +1
            float h;
            h = acc[t][0]; h = (h >= 0.f) ? h : 0.2f * h; sum0 += h * w2v.x;
            h = acc[t][1]; h = (h >= 0.f) ? h : 0.2f * h; sum0 += h * w2v.y;
            h = acc[t][2]; h = (h >= 0.f) ? h : 0.2f * h; sum1 += h * w2v.x;
            h = acc[t][3]; h = (h >= 0.f) ? h : 0.2f * h; sum1 += h * w2v.y;
        }
        sum0 += __shfl_xor_sync(0xFFFFFFFF, sum0, 1);
        sum0 += __shfl_xor_sync(0xFFFFFFFF, sum0, 2);
        sum1 += __shfl_xor_sync(0xFFFFFFFF, sum1, 1);
        sum1 += __shfl_xor_sync(0xFFFFFFFF, sum1, 2);
        float pv0 = (sum0 >= 0.f) ? sum0 : 0.2f * sum0;
        float pv1 = (sum1 >= 0.f) ? sum1 : 0.2f * sum1;
        if ((lid & 3) == 0) {
            int row = lid >> 2;
            float* dst = g_p + (size_t)p * B_SZ + rb * 128 + m0;
            dst[row] = pv0;
            dst[row + 8] = pv1;
        }
        float s1 = ((lid & 3) == 0) ? (pv0 + pv1) : 0.f;
        float s2 = ((lid & 3) == 0) ? (pv0 * pv0 + pv1 * pv1) : 0.f;
        #pragma unroll
        for (int m = 4; m < 32; m <<= 1) {
            s1 += __shfl_xor_sync(0xFFFFFFFF, s1, m);
            s2 += __shfl_xor_sync(0xFFFFFFFF, s2, m);
        }
        __syncthreads();
        float2* red = reinterpret_cast<float2*>(smem);
        if (lid == 0) red[wid] = make_float2(s1, s2);
        __syncthreads();
        if (tid == 0) {
            float t1 = 0.f, t2 = 0.f;
            #pragma unroll
            for (int w = 0; w < 8; w++) { t1 += red[w].x; t2 += red[w].y; }
            g_part[rb * P_N + p] = make_float2(t1, t2);
        }
    }
}

// ============ K2: reduce partials + collapse BN + global-L2 + projection into a_p, c ============
// 512 threads: thread (p = tid&127, quarter r = tid>>7) sums 32 rb's, smem-combine, then tree.
__global__ __launch_bounds__(512) void k2_finalize(
    const float* __restrict__ gamma, const float* __restrict__ beta,
    const float* __restrict__ Wd, const float* __restrict__ bdp) {
    const int tid = threadIdx.x;
    const int p = tid & 127;
    const int r4 = tid >> 7;

    double S1 = 0.0, S2 = 0.0;
    #pragma unroll 8
    for (int rb = r4 * 32; rb < r4 * 32 + 32; rb++) {
        float2 v = g_part[rb * P_N + p];
        S1 += (double)v.x;
        S2 += (double)v.y;
    }
    __shared__ double sh1[512], sh2[512];
    sh1[tid] = S1; sh2[tid] = S2;
    __syncthreads();

    __shared__ double sn[128], st[128];
    if (r4 == 0) {
        S1 = sh1[p] + sh1[p + 128] + sh1[p + 256] + sh1[p + 384];
        S2 = sh2[p] + sh2[p + 128] + sh2[p + 256] + sh2[p + 384];
        const double Bd = (double)B_SZ;
        double mean = S1 / Bd;
        double var = S2 / Bd - mean * mean;
        if (var < 0.0) var = 0.0;
        double sig2 = var + (double)BN_EPS;
        double inv_sigma = 1.0 / sqrt(sig2);
        double g = (double)gamma[p], bt = (double)beta[p], wd = (double)Wd[p];
        sn[p] = g * g * Bd * var / sig2 + Bd * bt * bt;
        st[p] = (bt - mean * g * inv_sigma) * wd;
        sh1[p] = inv_sigma;        // stash for after the tree
    }
    __syncthreads();
    for (int o = 64; o > 0; o >>= 1) {
        if (tid < o) { sn[tid] += sn[tid + o]; st[tid] += st[tid + o]; }
        __syncthreads();
    }
    if (r4 == 0) {
        double norm = sqrt(sn[0]);
        double g = (double)gamma[p], wd = (double)Wd[p];
        g_a[p] = (float)(g * wd * sh1[p] / norm);
        if (p == 0) g_c = (float)(st[0] / norm + (double)bdp[0]);
    }
}

// ============ K3: out[b] = sigmoid(sum_p p[b,p]*a_p + c) ============
// 32768 threads; thread (q = gid&7 -> 16 pathways, t = gid>>3 -> b-group of 4) does
// 16 float4 loads, butterfly-reduces over q lanes, lane q==0 writes float4 of sigmoids.
__global__ __launch_bounds__(256) void k3_out(float* __restrict__ out) {
    __shared__ float sa[128];
    __shared__ float sc;
    const int tid = threadIdx.x;
    if (tid < 128) sa[tid] = g_a[tid];
    if (tid == 0) sc = g_c;
    __syncthreads();

    const int gid = blockIdx.x * 256 + tid;
    const int q = gid & 7;                 // pathway chunk
    const int t = gid >> 3;                // float4 index over b (0..4095)
    const float4* pp = reinterpret_cast<const float4*>(g_p);

    float4 acc = make_float4(0.f, 0.f, 0.f, 0.f);
    #pragma unroll
    for (int i = 0; i < 16; i++) {
        int p = q * 16 + i;
        float4 v = pp[(size_t)p * (B_SZ / 4) + t];
        float a = sa[p];
        acc.x += v.x * a; acc.y += v.y * a; acc.z += v.z * a; acc.w += v.w * a;
    }
    #pragma unroll
    for (int m = 1; m < 8; m <<= 1) {
        acc.x += __shfl_xor_sync(0xFFFFFFFF, acc.x, m);
        acc.y += __shfl_xor_sync(0xFFFFFFFF, acc.y, m);
        acc.z += __shfl_xor_sync(0xFFFFFFFF, acc.z, m);
        acc.w += __shfl_xor_sync(0xFFFFFFFF, acc.w, m);
    }
    if (q == 0) {
        float4 o;
        o.x = 1.f / (1.f + expf(-(acc.x + sc)));
        o.y = 1.f / (1.f + expf(-(acc.y + sc)));
        o.z = 1.f / (1.f + expf(-(acc.z + sc)));
        o.w = 1.f / (1.f + expf(-(acc.w + sc)));
        reinterpret_cast<float4*>(out)[t] = o;
    }
}

// ============ launch ============
extern "C" void kernel_launch(void* const* d_in, const int* in_sizes, int n_in,
                              void* d_out, int out_size) {
    const float* x     = (const float*)d_in[0];
    const float* W1    = (const float*)d_in[1];
    const float* W2    = (const float*)d_in[2];
    const float* gamma = (const float*)d_in[3];
    const float* beta  = (const float*)d_in[4];
    const float* Wd    = (const float*)d_in[5];
    const float* bdp   = (const float*)d_in[6];
    float* out = (float*)d_out;

    k0_w1bf<<<1024, 256>>>(W1);
    k1_mma<<<dim3(B_SZ / 128, P_N), 256, 49152>>>(x, W2);
    k2_finalize<<<1, 512>>>(gamma, beta, Wd, bdp);
    k3_out<<<128, 256>>>(out);
}

// round 6
// speedup vs baseline: 1.1464x; 1.1071x over previous
#include <cuda_runtime.h>
#include <cuda_bf16.h>
#include <cstdint>

// ---------------- problem constants ----------------
#define B_SZ 16384
#define P_N  128
#define V_N  128
#define W_N  64
#define BN_EPS 1e-5

// ---------------- scratch (static device globals; no allocation) ----------------
__device__ float          g_p[P_N * B_SZ];          // p[pathway][batch], 8 MB
__device__ __nv_bfloat16  g_W1bf[P_N * W_N * V_N];  // bf16 W1, row-major [p][w][v], 2 MB
__device__ double         g_S1[P_N], g_S2[P_N];
__device__ float          g_a[P_N];
__device__ float          g_c;

__device__ __forceinline__ uint32_t smem_u32(const void* p) {
    uint32_t a;
    asm("{ .reg .u64 t; cvta.to.shared.u64 t, %1; cvt.u32.u64 %0, t; }" : "=r"(a) : "l"(p));
    return a;
}

// swizzled byte offset inside a [rows][128 bf16] tile (256 B per row)
__device__ __forceinline__ int swz(int row, int byte_in_row) {
    return row * 256 + (byte_in_row ^ ((row & 7) << 4));
}

__device__ __forceinline__ void ldmatrix_x4(uint32_t& r0, uint32_t& r1, uint32_t& r2, uint32_t& r3,
                                            uint32_t addr) {
    asm volatile("ldmatrix.sync.aligned.m8n8.x4.shared.b16 {%0,%1,%2,%3}, [%4];"
                 : "=r"(r0), "=r"(r1), "=r"(r2), "=r"(r3) : "r"(addr));
}

__device__ __forceinline__ void mma_bf16(float& c0, float& c1, float& c2, float& c3,
                                         uint32_t a0, uint32_t a1, uint32_t a2, uint32_t a3,
                                         uint32_t b0, uint32_t b1) {
    asm volatile("mma.sync.aligned.m16n8k16.row.col.f32.bf16.bf16.f32 "
                 "{%0,%1,%2,%3}, {%4,%5,%6,%7}, {%8,%9}, {%0,%1,%2,%3};"
                 : "+f"(c0), "+f"(c1), "+f"(c2), "+f"(c3)
                 : "r"(a0), "r"(a1), "r"(a2), "r"(a3), "r"(b0), "r"(b1));
}

// ============ K0: convert W1 fp32 -> bf16 row-major ============
__global__ __launch_bounds__(256) void k0_w1bf(const float* __restrict__ W1) {
    int idx = blockIdx.x * 256 + threadIdx.x;      // < 262144, each handles 4 elems
    float4 v = *reinterpret_cast<const float4*>(W1 + (size_t)idx * 4);
    __nv_bfloat162 lo = __float22bfloat162_rn(make_float2(v.x, v.y));
    __nv_bfloat162 hi = __float22bfloat162_rn(make_float2(v.z, v.w));
    uint2 pack = make_uint2(*reinterpret_cast<uint32_t*>(&lo), *reinterpret_cast<uint32_t*>(&hi));
    *reinterpret_cast<uint2*>(g_W1bf + (size_t)idx * 4) = pack;
}

// ============ K1: per-pathway [128x64x128] bf16 mma.sync + fused leaky/W2/leaky ============
// grid (B/128, P), 256 threads (8 warps). Warp w: rows m0 = 16*w.
// __launch_bounds__(256, 4): cap regs at 64 to force 4 CTAs/SM (192 KB smem <= 228 KB).
__global__ __launch_bounds__(256, 4) void k1_mma(const float* __restrict__ x,
                                                 const float* __restrict__ W2) {
    extern __shared__ char smem[];                 // [0,32768) xs swizzled, [32768,49152) ws swizzled
    const uint32_t sb = smem_u32(smem);
    const int tid = threadIdx.x;
    const int wid = tid >> 5;
    const int lid = tid & 31;
    const int rb = blockIdx.x;                     // 128-row batch block
    const int p  = blockIdx.y;                     // pathway

    // ---- load + convert x tile: 128 rows x 128 fp32 -> bf16 swizzled smem ----
    {
        const float* xrow = x + (size_t)rb * 128 * (P_N * V_N) + (size_t)p * V_N;
        #pragma unroll
        for (int i = 0; i < 16; i++) {
            int idx = tid + i * 256;               // < 4096
            int r = idx >> 5;
            int c = (idx & 31);                    // float4 index in row
            float4 v = *reinterpret_cast<const float4*>(xrow + (size_t)r * (P_N * V_N) + c * 4);
            __nv_bfloat162 lo = __float22bfloat162_rn(make_float2(v.x, v.y));
            __nv_bfloat162 hi = __float22bfloat162_rn(make_float2(v.z, v.w));
            uint2 pack = make_uint2(*reinterpret_cast<uint32_t*>(&lo), *reinterpret_cast<uint32_t*>(&hi));
            *reinterpret_cast<uint2*>(smem + swz(r, c * 8)) = pack;
        }
    }
    // ---- copy W1 bf16 tile: 64 rows x 128 -> swizzled smem ----
    {
        const uint4* wsrc = reinterpret_cast<const uint4*>(g_W1bf + (size_t)p * (W_N * V_N));
        #pragma unroll
        for (int i = 0; i < 4; i++) {
            int idx = tid + i * 256;               // < 1024 16B-chunks
            int n = idx >> 4;
            int kc = idx & 15;
            *reinterpret_cast<uint4*>(smem + 32768 + swz(n, kc * 16)) = wsrc[idx];
        }
    }
    __syncthreads();

    // ---- mainloop: warp computes [16 x 64], K=128 ----
    float acc[8][4];
    #pragma unroll
    for (int t = 0; t < 8; t++)
        #pragma unroll
        for (int j = 0; j < 4; j++) acc[t][j] = 0.f;

    const int m0 = wid * 16;
    const uint32_t a_row = m0 + (lid & 15);
    const uint32_t a_chunk = (lid >> 4) * 16;
    const int bg = lid >> 3;                        // 0..3 address group
    const int b_nrow_off = (lid & 7) + ((bg >= 2) ? 8 : 0);
    const int b_koff = (bg & 1) * 16;

    #pragma unroll
    for (int ks = 0; ks < 8; ks++) {
        const int kb = ks * 32;                     // byte offset of k-step in row
        uint32_t a0, a1, a2, a3;
        ldmatrix_x4(a0, a1, a2, a3, sb + swz(a_row, kb + a_chunk));
        #pragma unroll
        for (int t = 0; t < 4; t++) {
            uint32_t b0, b1, b2, b3;
            ldmatrix_x4(b0, b1, b2, b3,
                        sb + 32768 + swz(t * 16 + b_nrow_off, kb + b_koff));
            mma_bf16(acc[2*t][0], acc[2*t][1], acc[2*t][2], acc[2*t][3],
                     a0, a1, a2, a3, b0, b1);
            mma_bf16(acc[2*t+1][0], acc[2*t+1][1], acc[2*t+1][2], acc[2*t+1][3],
                     a0, a1, a2, a3, b2, b3);
        }
    }

    // ---- epilogue: h=leaky(acc); dot with W2 over n; p=leaky(dot) ----
    {
        const float2* w2p = reinterpret_cast<const float2*>(W2 + (size_t)p * W_N);
        float sum0 = 0.f, sum1 = 0.f;               // rows (lid>>2), (lid>>2)+8
        #pragma unroll
        for (int t = 0; t < 8; t++) {
            float2 w2v = __ldg(&w2p[t * 4 + (lid & 3)]);   // cols t*8 + (lid&3)*2, +1
            float h;
            h = acc[t][0]; h = (h >= 0.f) ? h : 0.2f * h; sum0 += h * w2v.x;
            h = acc[t][1]; h = (h >= 0.f) ? h : 0.2f * h; sum0 += h * w2v.y;
            h = acc[t][2]; h = (h >= 0.f) ? h : 0.2f * h; sum1 += h * w2v.x;
            h = acc[t][3]; h = (h >= 0.f) ? h : 0.2f * h; sum1 += h * w2v.y;
        }
        // reduce across the 4 lanes of each quad (they share the same rows)
        sum0 += __shfl_xor_sync(0xFFFFFFFF, sum0, 1);
        sum0 += __shfl_xor_sync(0xFFFFFFFF, sum0, 2);
        sum1 += __shfl_xor_sync(0xFFFFFFFF, sum1, 1);
        sum1 += __shfl_xor_sync(0xFFFFFFFF, sum1, 2);
        if ((lid & 3) == 0) {
            int row = lid >> 2;
            float pv0 = (sum0 >= 0.f) ? sum0 : 0.2f * sum0;
            float pv1 = (sum1 >= 0.f) ? sum1 : 0.2f * sum1;
            float* dst = g_p + (size_t)p * B_SZ + rb * 128 + m0;
            dst[row] = pv0;
            dst[row + 8] = pv1;
        }
    }
}

// ============ K2a: per-pathway sum / sumsq (float4 loads, fp64 accum) ============
__global__ __launch_bounds__(256) void k2a_reduce() {
    const int p = blockIdx.x;
    const int tid = threadIdx.x;
    const float4* col = reinterpret_cast<const float4*>(g_p + (size_t)p * B_SZ);
    double a1 = 0.0, a2 = 0.0;
    #pragma unroll 4
    for (int i = tid; i < B_SZ / 4; i += 256) {
        float4 v = col[i];
        a1 += (double)v.x + (double)v.y + (double)v.z + (double)v.w;
        a2 += (double)v.x * v.x + (double)v.y * v.y + (double)v.z * v.z + (double)v.w * v.w;
    }
    __shared__ double s1[256], s2[256];
    s1[tid] = a1; s2[tid] = a2;
    __syncthreads();
    for (int o = 128; o > 0; o >>= 1) {
        if (tid < o) { s1[tid] += s1[tid + o]; s2[tid] += s2[tid + o]; }
        __syncthreads();
    }
    if (tid == 0) { g_S1[p] = s1[0]; g_S2[p] = s2[0]; }
}

// ============ K2b: collapse BN + global-L2 + disease projection into a_p, c ============
__global__ __launch_bounds__(128) void k2b_finalize(
    const float* __restrict__ gamma, const float* __restrict__ beta,
    const float* __restrict__ Wd, const float* __restrict__ bdp) {
    const int p = threadIdx.x;
    const double Bd = (double)B_SZ;
    double mean = g_S1[p] / Bd;
    double var = g_S2[p] / Bd - mean * mean;
    if (var < 0.0) var = 0.0;
    double sig2 = var + (double)BN_EPS;
    double inv_sigma = 1.0 / sqrt(sig2);
    double g = (double)gamma[p], bt = (double)beta[p], wd = (double)Wd[p];
    double nsq = g * g * Bd * var / sig2 + Bd * bt * bt;   // sum over b of pn^2 for this p
    double t = (bt - mean * g * inv_sigma) * wd;

    __shared__ double sn[128], st[128];
    sn[p] = nsq; st[p] = t;
    __syncthreads();
    for (int o = 64; o > 0; o >>= 1) {
        if (p < o) { sn[p] += sn[p + o]; st[p] += st[p + o]; }
        __syncthreads();
    }
    __shared__ double norm_s, T_s;
    if (p == 0) { norm_s = sqrt(sn[0]); T_s = st[0]; }
    __syncthreads();
    double norm = norm_s;
    g_a[p] = (float)(g * wd * inv_sigma / norm);
    if (p == 0) g_c = (float)(T_s / norm + (double)bdp[0]);
}

// ============ K3: out[b] = sigmoid(sum_p p[b,p]*a_p + c) ============
// 65536 threads; thread (q = gid&15 -> 8 pathways, t = gid>>4 -> b-group of 4) does
// 8 float4 loads, butterfly-reduces over the 16 q lanes, lane q==0 writes float4.
__global__ __launch_bounds__(256) void k3_out(float* __restrict__ out) {
    __shared__ float sa[128];
    __shared__ float sc;
    const int tid = threadIdx.x;
    if (tid < 128) sa[tid] = g_a[tid];
    if (tid == 0) sc = g_c;
    __syncthreads();

    const int gid = blockIdx.x * 256 + tid;
    const int q = gid & 15;                // pathway chunk (8 pathways)
    const int t = gid >> 4;                // float4 index over b (0..4095)
    const float4* pp = reinterpret_cast<const float4*>(g_p);

    float4 acc = make_float4(0.f, 0.f, 0.f, 0.f);
    #pragma unroll
    for (int i = 0; i < 8; i++) {
        int p = q * 8 + i;
        float4 v = pp[(size_t)p * (B_SZ / 4) + t];
        float a = sa[p];
        acc.x += v.x * a; acc.y += v.y * a; acc.z += v.z * a; acc.w += v.w * a;
    }
    #pragma unroll
    for (int m = 1; m < 16; m <<= 1) {
        acc.x += __shfl_xor_sync(0xFFFFFFFF, acc.x, m);
        acc.y += __shfl_xor_sync(0xFFFFFFFF, acc.y, m);
        acc.z += __shfl_xor_sync(0xFFFFFFFF, acc.z, m);
        acc.w += __shfl_xor_sync(0xFFFFFFFF, acc.w, m);
    }
    if (q == 0) {
        float4 o;
        o.x = 1.f / (1.f + expf(-(acc.x + sc)));
        o.y = 1.f / (1.f + expf(-(acc.y + sc)));
        o.z = 1.f / (1.f + expf(-(acc.z + sc)));
        o.w = 1.f / (1.f + expf(-(acc.w + sc)));
        reinterpret_cast<float4*>(out)[t] = o;
    }
}

// ============ launch ============
extern "C" void kernel_launch(void* const* d_in, const int* in_sizes, int n_in,
                              void* d_out, int out_size) {
    const float* x     = (const float*)d_in[0];
    const float* W1    = (const float*)d_in[1];
    const float* W2    = (const float*)d_in[2];
    const float* gamma = (const float*)d_in[3];
    const float* beta  = (const float*)d_in[4];
    const float* Wd    = (const float*)d_in[5];
    const float* bdp   = (const float*)d_in[6];
    float* out = (float*)d_out;

    k0_w1bf<<<1024, 256>>>(W1);
    k1_mma<<<dim3(B_SZ / 128, P_N), 256, 49152>>>(x, W2);
    k2a_reduce<<<P_N, 256>>>();
    k2b_finalize<<<1, 128>>>(gamma, beta, Wd, bdp);
    k3_out<<<256, 256>>>(out);
}

// round 7
// speedup vs baseline: 1.1689x; 1.0196x over previous
#include <cuda_runtime.h>
#include <cuda_bf16.h>
#include <cstdint>

// ---------------- problem constants ----------------
#define B_SZ 16384
#define P_N  128
#define V_N  128
#define W_N  64
#define BN_EPS 1e-5

// ---------------- scratch (static device globals; no allocation) ----------------
__device__ float          g_p[P_N * B_SZ];          // p[pathway][batch], 8 MB
__device__ __nv_bfloat16  g_W1bf[P_N * W_N * V_N];  // bf16 W1, row-major [p][w][v], 2 MB
__device__ double         g_S1[P_N], g_S2[P_N];

__device__ __forceinline__ uint32_t smem_u32(const void* p) {
    uint32_t a;
    asm("{ .reg .u64 t; cvta.to.shared.u64 t, %1; cvt.u32.u64 %0, t; }" : "=r"(a) : "l"(p));
    return a;
}

// swizzled byte offset inside a [rows][128 bf16] tile (256 B per row)
__device__ __forceinline__ int swz(int row, int byte_in_row) {
    return row * 256 + (byte_in_row ^ ((row & 7) << 4));
}

__device__ __forceinline__ void ldmatrix_x4(uint32_t& r0, uint32_t& r1, uint32_t& r2, uint32_t& r3,
                                            uint32_t addr) {
    asm volatile("ldmatrix.sync.aligned.m8n8.x4.shared.b16 {%0,%1,%2,%3}, [%4];"
                 : "=r"(r0), "=r"(r1), "=r"(r2), "=r"(r3) : "r"(addr));
}

__device__ __forceinline__ void mma_bf16(float& c0, float& c1, float& c2, float& c3,
                                         uint32_t a0, uint32_t a1, uint32_t a2, uint32_t a3,
                                         uint32_t b0, uint32_t b1) {
    asm volatile("mma.sync.aligned.m16n8k16.row.col.f32.bf16.bf16.f32 "
                 "{%0,%1,%2,%3}, {%4,%5,%6,%7}, {%8,%9}, {%0,%1,%2,%3};"
                 : "+f"(c0), "+f"(c1), "+f"(c2), "+f"(c3)
                 : "r"(a0), "r"(a1), "r"(a2), "r"(a3), "r"(b0), "r"(b1));
}

// ============ K0: convert W1 fp32 -> bf16 row-major ============
__global__ __launch_bounds__(256) void k0_w1bf(const float* __restrict__ W1) {
    int idx = blockIdx.x * 256 + threadIdx.x;      // < 262144, each handles 4 elems
    float4 v = *reinterpret_cast<const float4*>(W1 + (size_t)idx * 4);
    __nv_bfloat162 lo = __float22bfloat162_rn(make_float2(v.x, v.y));
    __nv_bfloat162 hi = __float22bfloat162_rn(make_float2(v.z, v.w));
    uint2 pack = make_uint2(*reinterpret_cast<uint32_t*>(&lo), *reinterpret_cast<uint32_t*>(&hi));
    *reinterpret_cast<uint2*>(g_W1bf + (size_t)idx * 4) = pack;
}

// ============ K1: per-pathway [128x64x128] bf16 mma.sync + fused leaky/W2/leaky ============
// grid (B/128, P), 256 threads (8 warps). Warp w: rows m0 = 16*w.  (byte-identical to R6)
__global__ __launch_bounds__(256, 4) void k1_mma(const float* __restrict__ x,
                                                 const float* __restrict__ W2) {
    extern __shared__ char smem[];                 // [0,32768) xs swizzled, [32768,49152) ws swizzled
    const uint32_t sb = smem_u32(smem);
    const int tid = threadIdx.x;
    const int wid = tid >> 5;
    const int lid = tid & 31;
    const int rb = blockIdx.x;                     // 128-row batch block
    const int p  = blockIdx.y;                     // pathway

    // ---- load + convert x tile: 128 rows x 128 fp32 -> bf16 swizzled smem ----
    {
        const float* xrow = x + (size_t)rb * 128 * (P_N * V_N) + (size_t)p * V_N;
        #pragma unroll
        for (int i = 0; i < 16; i++) {
            int idx = tid + i * 256;               // < 4096
            int r = idx >> 5;
            int c = (idx & 31);                    // float4 index in row
            float4 v = *reinterpret_cast<const float4*>(xrow + (size_t)r * (P_N * V_N) + c * 4);
            __nv_bfloat162 lo = __float22bfloat162_rn(make_float2(v.x, v.y));
            __nv_bfloat162 hi = __float22bfloat162_rn(make_float2(v.z, v.w));
            uint2 pack = make_uint2(*reinterpret_cast<uint32_t*>(&lo), *reinterpret_cast<uint32_t*>(&hi));
            *reinterpret_cast<uint2*>(smem + swz(r, c * 8)) = pack;
        }
    }
    // ---- copy W1 bf16 tile: 64 rows x 128 -> swizzled smem ----
    {
        const uint4* wsrc = reinterpret_cast<const uint4*>(g_W1bf + (size_t)p * (W_N * V_N));
        #pragma unroll
        for (int i = 0; i < 4; i++) {
            int idx = tid + i * 256;               // < 1024 16B-chunks
            int n = idx >> 4;
            int kc = idx & 15;
            *reinterpret_cast<uint4*>(smem + 32768 + swz(n, kc * 16)) = wsrc[idx];
        }
    }
    __syncthreads();

    // ---- mainloop: warp computes [16 x 64], K=128 ----
    float acc[8][4];
    #pragma unroll
    for (int t = 0; t < 8; t++)
        #pragma unroll
        for (int j = 0; j < 4; j++) acc[t][j] = 0.f;

    const int m0 = wid * 16;
    const uint32_t a_row = m0 + (lid & 15);
    const uint32_t a_chunk = (lid >> 4) * 16;
    const int bg = lid >> 3;                        // 0..3 address group
    const int b_nrow_off = (lid & 7) + ((bg >= 2) ? 8 : 0);
    const int b_koff = (bg & 1) * 16;

    #pragma unroll
    for (int ks = 0; ks < 8; ks++) {
        const int kb = ks * 32;                     // byte offset of k-step in row
        uint32_t a0, a1, a2, a3;
        ldmatrix_x4(a0, a1, a2, a3, sb + swz(a_row, kb + a_chunk));
        #pragma unroll
        for (int t = 0; t < 4; t++) {
            uint32_t b0, b1, b2, b3;
            ldmatrix_x4(b0, b1, b2, b3,
                        sb + 32768 + swz(t * 16 + b_nrow_off, kb + b_koff));
            mma_bf16(acc[2*t][0], acc[2*t][1], acc[2*t][2], acc[2*t][3],
                     a0, a1, a2, a3, b0, b1);
            mma_bf16(acc[2*t+1][0], acc[2*t+1][1], acc[2*t+1][2], acc[2*t+1][3],
                     a0, a1, a2, a3, b2, b3);
        }
    }

    // ---- epilogue: h=leaky(acc); dot with W2 over n; p=leaky(dot) ----
    {
        const float2* w2p = reinterpret_cast<const float2*>(W2 + (size_t)p * W_N);
        float sum0 = 0.f, sum1 = 0.f;               // rows (lid>>2), (lid>>2)+8
        #pragma unroll
        for (int t = 0; t < 8; t++) {
            float2 w2v = __ldg(&w2p[t * 4 + (lid & 3)]);   // cols t*8 + (lid&3)*2, +1
            float h;
            h = acc[t][0]; h = (h >= 0.f) ? h : 0.2f * h; sum0 += h * w2v.x;
            h = acc[t][1]; h = (h >= 0.f) ? h : 0.2f * h; sum0 += h * w2v.y;
            h = acc[t][2]; h = (h >= 0.f) ? h : 0.2f * h; sum1 += h * w2v.x;
            h = acc[t][3]; h = (h >= 0.f) ? h : 0.2f * h; sum1 += h * w2v.y;
        }
        sum0 += __shfl_xor_sync(0xFFFFFFFF, sum0, 1);
        sum0 += __shfl_xor_sync(0xFFFFFFFF, sum0, 2);
        sum1 += __shfl_xor_sync(0xFFFFFFFF, sum1, 1);
        sum1 += __shfl_xor_sync(0xFFFFFFFF, sum1, 2);
        if ((lid & 3) == 0) {
            int row = lid >> 2;
            float pv0 = (sum0 >= 0.f) ? sum0 : 0.2f * sum0;
            float pv1 = (sum1 >= 0.f) ? sum1 : 0.2f * sum1;
            float* dst = g_p + (size_t)p * B_SZ + rb * 128 + m0;
            dst[row] = pv0;
            dst[row + 8] = pv1;
        }
    }
}

// ============ K2a: per-pathway sum / sumsq (float4 loads, fp64 accum) ============
__global__ __launch_bounds__(256) void k2a_reduce() {
    const int p = blockIdx.x;
    const int tid = threadIdx.x;
    const float4* col = reinterpret_cast<const float4*>(g_p + (size_t)p * B_SZ);
    double a1 = 0.0, a2 = 0.0;
    #pragma unroll 4
    for (int i = tid; i < B_SZ / 4; i += 256) {
        float4 v = col[i];
        a1 += (double)v.x + (double)v.y + (double)v.z + (double)v.w;
        a2 += (double)v.x * v.x + (double)v.y * v.y + (double)v.z * v.z + (double)v.w * v.w;
    }
    __shared__ double s1[256], s2[256];
    s1[tid] = a1; s2[tid] = a2;
    __syncthreads();
    for (int o = 128; o > 0; o >>= 1) {
        if (tid < o) { s1[tid] += s1[tid + o]; s2[tid] += s2[tid + o]; }
        __syncthreads();
    }
    if (tid == 0) { g_S1[p] = s1[0]; g_S2[p] = s2[0]; }
}

// ============ K3: per-block BN/L2/projection finalize + out[b] = sigmoid(dot + c) ============
// Every block redundantly computes the 128 coefficients from (S1,S2) — 2 KB, L2-resident,
// parallel across blocks (replaces the 8.8us serialized 1-block k2b).
// Then: thread (q = gid&15 -> 8 pathways, t = gid>>4 -> b-group of 4): 8 float4 loads,
// butterfly over 16 q-lanes, lane q==0 writes float4 of sigmoids.
__global__ __launch_bounds__(256) void k3_out(float* __restrict__ out,
                                              const float* __restrict__ gamma,
                                              const float* __restrict__ beta,
                                              const float* __restrict__ Wd,
                                              const float* __restrict__ bdp) {
    __shared__ float sa[128];        // final coefficient per pathway
    __shared__ float sw[128];        // scratch: g*wd*inv_sigma
    __shared__ float sn[128], st[128];
    __shared__ float sc_s;
    const int tid = threadIdx.x;

    // ---- in-block finalize (threads 0..127) ----
    if (tid < 128) {
        const int p = tid;
        const double invB = 1.0 / (double)B_SZ;
        double mean_d = g_S1[p] * invB;
        double var_d = g_S2[p] * invB - mean_d * mean_d;   // fp64: cancellation-sensitive
        float var = (float)(var_d < 0.0 ? 0.0 : var_d);
        float mean = (float)mean_d;
        float sig2 = var + (float)BN_EPS;
        float inv_sigma = rsqrtf(sig2);
        float g = gamma[p], bt = beta[p], wd = Wd[p];
        sn[p] = g * g * (float)B_SZ * var / sig2 + (float)B_SZ * bt * bt;
        st[p] = (bt - mean * g * inv_sigma) * wd;
        sw[p] = g * wd * inv_sigma;
    }
    __syncthreads();
    // tree-reduce sn (norm^2) and st (T) over 128 pathways
    for (int o = 64; o > 0; o >>= 1) {
        if (tid < o) { sn[tid] += sn[tid + o]; st[tid] += st[tid + o]; }
        __syncthreads();
    }
    if (tid < 128) {
        float inv_norm = rsqrtf(sn[0]);
        sa[tid] = sw[tid] * inv_norm;
        if (tid == 0) sc_s = st[0] * inv_norm + bdp[0];
    }
    __syncthreads();
    const float sc = sc_s;

    // ---- dot + sigmoid ----
    const int gid = blockIdx.x * 256 + tid;
    const int q = gid & 15;                // pathway chunk (8 pathways)
    const int t = gid >> 4;                // float4 index over b (0..4095)
    const float4* pp = reinterpret_cast<const float4*>(g_p);

    float4 acc = make_float4(0.f, 0.f, 0.f, 0.f);
    #pragma unroll
    for (int i = 0; i < 8; i++) {
        int p = q * 8 + i;
        float4 v = pp[(size_t)p * (B_SZ / 4) + t];
        float a = sa[p];
        acc.x += v.x * a; acc.y += v.y * a; acc.z += v.z * a; acc.w += v.w * a;
    }
    #pragma unroll
    for (int m = 1; m < 16; m <<= 1) {
        acc.x += __shfl_xor_sync(0xFFFFFFFF, acc.x, m);
        acc.y += __shfl_xor_sync(0xFFFFFFFF, acc.y, m);
        acc.z += __shfl_xor_sync(0xFFFFFFFF, acc.z, m);
        acc.w += __shfl_xor_sync(0xFFFFFFFF, acc.w, m);
    }
    if (q == 0) {
        float4 o;
        o.x = 1.f / (1.f + expf(-(acc.x + sc)));
        o.y = 1.f / (1.f + expf(-(acc.y + sc)));
        o.z = 1.f / (1.f + expf(-(acc.z + sc)));
        o.w = 1.f / (1.f + expf(-(acc.w + sc)));
        reinterpret_cast<float4*>(out)[t] = o;
    }
}

// ============ launch ============
extern "C" void kernel_launch(void* const* d_in, const int* in_sizes, int n_in,
                              void* d_out, int out_size) {
    const float* x     = (const float*)d_in[0];
    const float* W1    = (const float*)d_in[1];
    const float* W2    = (const float*)d_in[2];
    const float* gamma = (const float*)d_in[3];
    const float* beta  = (const float*)d_in[4];
    const float* Wd    = (const float*)d_in[5];
    const float* bdp   = (const float*)d_in[6];
    float* out = (float*)d_out;

    k0_w1bf<<<1024, 256>>>(W1);
    k1_mma<<<dim3(B_SZ / 128, P_N), 256, 49152>>>(x, W2);
    k2a_reduce<<<P_N, 256>>>();
    k3_out<<<256, 256>>>(out, gamma, beta, Wd, bdp);
}